// round 2
// baseline (speedup 1.0000x reference)
#include <cuda_runtime.h>
#include <math.h>

// Problem constants (fixed by the benchmark shapes)
#define Bn 256
#define Tn 1024
#define Cn 256          // classes, blank = Cn-1
#define Ln 128
#define Sn 257          // 2L+1 extended states
#define SPAD 260        // padded alpha row
#define NTH 288         // 9 full warps, >= Sn
#define EDEAD (-(1 << 28))

// exact 2^d for d in [-126, 0]; 0.0f below (safe per-state flush)
__device__ __forceinline__ float p2f(int d) {
    return (d > -127) ? __int_as_float((127 + d) << 23) : 0.0f;
}

__global__ void __launch_bounds__(NTH)
ctc_fwd_kernel(const int* __restrict__ labels,
               const float* __restrict__ ypred,
               float* __restrict__ out)
{
    __shared__ float2 A[2][SPAD];      // per-state (mantissa, exponent-as-int) pairs
    __shared__ float  prow[2][Cn];     // staged probability rows (+eps)
    __shared__ float2 fin[2];

    const int b   = blockIdx.x;
    const int tid = threadIdx.x;
    const int s   = tid;
    const bool active = (s < Sn);
    const float* __restrict__ row = ypred + (size_t)b * (size_t)(Tn * Cn);

    // Extended label sequence: even s -> blank (Cn-1), odd s -> labels[(s-1)/2]
    int c = Cn - 1;
    bool skip = false;
    if (active && (s & 1)) {
        c = __ldg(labels + b * Ln + (s >> 1));
        if (s >= 3) skip = (c != __ldg(labels + b * Ln + ((s - 2) >> 1)));
    }

    // t = 0 init: states 0,1 live with value y_pred + eps; everything else dead
    float m0 = 0.0f;
    int   e0 = EDEAD;
    if (active && s < 2) {
        float v  = row[c] + 1e-7f;
        int bits = __float_as_int(v);
        e0 = ((bits >> 23) & 0xFF) - 127;
        m0 = __int_as_float((bits & 0x807FFFFF) | 0x3F800000);  // mantissa in [1,2)
    }
    if (tid < SPAD) {
        float2 dead = make_float2(0.0f, __int_as_float(EDEAD));
        A[1][tid] = dead;
        float2 init = dead;
        if (active && tid < 2) init = make_float2(m0, __int_as_float(e0));
        A[0][tid] = init;
    }
    if (tid < Cn) prow[1][tid] = row[Cn + tid] + 1e-7f;          // frame 1 staged
    float vpre = (tid < Cn) ? row[2 * Cn + tid] : 0.0f;          // frame 2 prefetch
    __syncthreads();

    int cur = 0;
    const float2 dead2 = make_float2(0.0f, __int_as_float(EDEAD));

    for (int t = 1; t < Tn; ++t) {
        const float2* __restrict__ ar = A[cur];
        float2*       __restrict__ aw = A[cur ^ 1];
        const float*  __restrict__ pr = prow[t & 1];
        float*        __restrict__ pw = prow[(t + 1) & 1];

        if (active) {
            float2 v1 = (s >= 1) ? ar[s - 1] : dead2;
            float2 v2 = (s >= 2) ? ar[s - 2] : dead2;
            int e1 = __float_as_int(v1.y);
            int e2 = skip ? __float_as_int(v2.y) : EDEAD;

            int emax = max(e0, max(e1, e2));
            float sum = fmaf(m0,   p2f(e0 - emax),
                        fmaf(v1.x, p2f(e1 - emax),
                             v2.x * p2f(e2 - emax)));

            float p = pr[c];
            float v = p * sum;                        // v == 0 or v >= ~1e-7 (normal)

            int bits = __float_as_int(v);
            int ib   = ((bits >> 23) & 0xFF) - 127;   // v==0 -> ib=-127 (stays dead)
            e0 = emax + ib;
            m0 = __int_as_float((bits & 0x807FFFFF) | 0x3F800000);
            aw[s] = make_float2(m0, __int_as_float(e0));
        }

        // Stage frame t+1 into the other slot; prefetch frame t+2
        if (tid < Cn) {
            pw[tid] = vpre + 1e-7f;
            int t2 = t + 2;
            vpre = (t2 < Tn) ? row[(size_t)t2 * Cn + tid] : 0.0f;
        }

        __syncthreads();
        cur ^= 1;
    }

    // loss = -( log(m1*2^e1 + m2*2^e2) )
    if (s == Sn - 1) fin[0] = make_float2(m0, __int_as_float(e0));
    if (s == Sn - 2) fin[1] = make_float2(m0, __int_as_float(e0));
    __syncthreads();
    if (tid == 0) {
        float ma = fin[0].x; int ea = __float_as_int(fin[0].y);
        float mb = fin[1].x; int eb = __float_as_int(fin[1].y);
        int em = max(ea, eb);
        float tot = fmaf(ma, p2f(ea - em), mb * p2f(eb - em));
        out[b] = -(logf(tot) + (float)em * 0.69314718055994530942f);
    }
}

extern "C" void kernel_launch(void* const* d_in, const int* in_sizes, int n_in,
                              void* d_out, int out_size)
{
    const int*   labels;
    const float* ypred;
    if (in_sizes[0] == Bn * Ln) {
        labels = (const int*)d_in[0];
        ypred  = (const float*)d_in[1];
    } else {
        labels = (const int*)d_in[1];
        ypred  = (const float*)d_in[0];
    }
    ctc_fwd_kernel<<<Bn, NTH>>>(labels, ypred, (float*)d_out);
}

// round 3
// speedup vs baseline: 1.7341x; 1.7341x over previous
#include <cuda_runtime.h>
#include <math.h>

// Problem constants (fixed by the benchmark shapes)
#define Bn 256
#define Tn 1024
#define Cn 256          // classes, blank = Cn-1
#define Ln 128
#define Sn 257          // 2L+1 extended states
#define Kj 9            // states per lane (32*9 = 288 >= 257)
#define EDEAD (-(1 << 28))

// exact 2^d for d in [-126, 0]; 0.0f below (safe per-state flush)
__device__ __forceinline__ float p2f(int d) {
    return (d > -127) ? __int_as_float((127 + d) << 23) : 0.0f;
}

// One forward-recurrence step for frame `tcur`, consuming p-bank `u` and
// reloading it with frame tcur+4 (clamped). All state in registers.
#define STEP(u, tcur) do {                                                     \
    float sm1 = __shfl_up_sync(0xffffffffu, m[Kj-1], 1);                       \
    int   se1 = __shfl_up_sync(0xffffffffu, e[Kj-1], 1);                       \
    float sm2 = __shfl_up_sync(0xffffffffu, m[Kj-2], 1);                       \
    int   se2 = __shfl_up_sync(0xffffffffu, e[Kj-2], 1);                       \
    if (lane == 0) { se1 = EDEAD; se2 = EDEAD; }                               \
    _Pragma("unroll")                                                          \
    for (int j = Kj - 1; j >= 0; --j) {                                        \
        float m1 = (j >= 1) ? m[j-1] : sm1;                                    \
        int   e1 = (j >= 1) ? e[j-1] : se1;                                    \
        float m2 = (j >= 2) ? m[j-2] : ((j == 1) ? sm1 : sm2);                 \
        int   e2 = (j >= 2) ? e[j-2] : ((j == 1) ? se1 : se2);                 \
        e2 += skipadd[j];                                                      \
        int emax = max(e[j], max(e1, e2));                                     \
        float sum = fmaf(m[j], p2f(e[j] - emax),                               \
                    fmaf(m1,   p2f(e1   - emax),                               \
                         m2  * p2f(e2   - emax)));                             \
        float v = (pv##u[j] + 1e-7f) * sum;                                    \
        int bits = __float_as_int(v);                                          \
        e[j] = emax + (((bits >> 23) & 0xFF) - 127);                           \
        m[j] = __int_as_float((bits & 0x807FFFFF) | 0x3F800000);               \
    }                                                                          \
    {                                                                          \
        int tf = (tcur) + 4; if (tf > Tn - 1) tf = Tn - 1;                     \
        const float* __restrict__ rr = row + (size_t)tf * Cn;                  \
        _Pragma("unroll")                                                      \
        for (int j = 0; j < Kj; ++j) pv##u[j] = __ldg(rr + c[j]);              \
    }                                                                          \
} while (0)

__global__ void __launch_bounds__(64)
ctc_warp_kernel(const int* __restrict__ labels,
                const float* __restrict__ ypred,
                float* __restrict__ out)
{
    const int lane = threadIdx.x & 31;
    const int warp = threadIdx.x >> 5;
    const int b    = blockIdx.x * 2 + warp;          // one batch element per warp
    const float* __restrict__ row = ypred + (size_t)b * (size_t)(Tn * Cn);
    const int s0 = lane * Kj;

    int   c[Kj];        // class per state (blank for even/dead)
    int   skipadd[Kj];  // 0 if skip transition allowed, EDEAD otherwise
    float m[Kj];        // mantissa in [1,2), 0 if dead
    int   e[Kj];        // base-2 exponent, EDEAD if dead

    #pragma unroll
    for (int j = 0; j < Kj; ++j) {
        int s = s0 + j;
        bool alive = (s < Sn);
        int ci = Cn - 1;
        int sk = EDEAD;
        if (alive && (s & 1)) {
            ci = __ldg(labels + b * Ln + (s >> 1));
            if (s >= 3) {
                int cp = __ldg(labels + b * Ln + ((s - 2) >> 1));
                if (ci != cp) sk = 0;
            }
        }
        c[j] = ci;
        skipadd[j] = sk;
        if (alive && s < 2) {                         // t = 0 init
            float v = __ldg(row + ci) + 1e-7f;
            int bits = __float_as_int(v);
            e[j] = ((bits >> 23) & 0xFF) - 127;
            m[j] = __int_as_float((bits & 0x807FFFFF) | 0x3F800000);
        } else { m[j] = 0.0f; e[j] = EDEAD; }
    }

    // Preload probability banks for frames 1..4
    float pv0[Kj], pv1[Kj], pv2[Kj], pv3[Kj];
    #pragma unroll
    for (int j = 0; j < Kj; ++j) {
        pv0[j] = __ldg(row + 1 * Cn + c[j]);
        pv1[j] = __ldg(row + 2 * Cn + c[j]);
        pv2[j] = __ldg(row + 3 * Cn + c[j]);
        pv3[j] = __ldg(row + 4 * Cn + c[j]);
    }

    // Main loop: t = 1 .. 1020 (255 x 4), then 3 tail steps
    int t = 1;
    #pragma unroll 1
    for (int it = 0; it < (Tn - 4) / 4; ++it) {
        STEP(0, t);
        STEP(1, t + 1);
        STEP(2, t + 2);
        STEP(3, t + 3);
        t += 4;
    }
    STEP(0, Tn - 3);   // t = 1021, bank 0
    STEP(1, Tn - 2);   // t = 1022, bank 1
    STEP(2, Tn - 1);   // t = 1023, bank 2

    // States Sn-2 = 255 (lane 28, j=3) and Sn-1 = 256 (lane 28, j=4)
    if (lane == 28) {
        int em = max(e[3], e[4]);
        float tot = fmaf(m[3], p2f(e[3] - em), m[4] * p2f(e[4] - em));
        out[b] = -(logf(tot) + (float)em * 0.69314718055994530942f);
    }
}

extern "C" void kernel_launch(void* const* d_in, const int* in_sizes, int n_in,
                              void* d_out, int out_size)
{
    const int*   labels;
    const float* ypred;
    if (in_sizes[0] == Bn * Ln) {
        labels = (const int*)d_in[0];
        ypred  = (const float*)d_in[1];
    } else {
        labels = (const int*)d_in[1];
        ypred  = (const float*)d_in[0];
    }
    ctc_warp_kernel<<<Bn / 2, 64>>>(labels, ypred, (float*)d_out);
}

// round 4
// speedup vs baseline: 2.2797x; 1.3147x over previous
#include <cuda_runtime.h>
#include <math.h>

// Problem constants (fixed by the benchmark shapes)
#define Bn 256
#define Tn 1024
#define Cn 256          // classes, blank = Cn-1
#define Ln 128
#define Sn 257          // 2L+1 extended states
#define EDEAD (-(1 << 28))

// exact 2^d for d in [-126, 0]; 0.0f below (per-quad relative flush)
__device__ __forceinline__ float p2f(int d) {
    return (d > -127) ? __int_as_float((127 + d) << 23) : 0.0f;
}

// Quad block-float update. States (a..a+3), a even:
//   even states: blank prob pbe, no skip; odd states: label probs, skip k*.
// Inputs: quad (m_0..m_3, E), prev-quad top (pm3, pE).
#define QUPD(M0, M1, M2, M3, E, pm3, pE, k1, k3, pbe, pe1, pe3) do {          \
    int   _emax = max((E), (pE));                                             \
    float _scq  = p2f((E)  - _emax);                                          \
    float _scp  = p2f((pE) - _emax);                                          \
    float _x0 = (M0) * _scq, _x1 = (M1) * _scq;                               \
    float _x2 = (M2) * _scq, _x3 = (M3) * _scq;                               \
    float _y3 = (pm3) * _scp;                                                 \
    float _n0 = _x0 + _y3;                                                    \
    float _n1 = fmaf((k1), _y3, _x0) + _x1;                                   \
    float _n2 = _x2 + _x1;                                                    \
    float _n3 = fmaf((k3), _x1, _x2) + _x3;                                   \
    float _v0 = (pbe) * _n0, _v1 = (pe1) * _n1;                               \
    float _v2 = (pbe) * _n2, _v3 = (pe3) * _n3;                               \
    float _mx = fmaxf(fmaxf(_v0, _v1), fmaxf(_v2, _v3));                      \
    int   _ef = __float_as_int(_mx) >> 23;                                    \
    float _scr = __int_as_float((254 - _ef) << 23);  /* 2^(127-ef), exact */  \
    (E)  = _emax + _ef - 127;                                                 \
    (M0) = _v0 * _scr; (M1) = _v1 * _scr;                                     \
    (M2) = _v2 * _scr; (M3) = _v3 * _scr;                                     \
} while (0)

// One time step consuming probability bank u, then refilling it with frame
// tcur+4 (clamped). Order: shfl old boundary -> quad1 (uses old quad0) ->
// quad0 (uses shfl'd old lane-1 quad1) -> state 256 (uses old quad1 top).
#define STEP(u, tcur) do {                                                    \
    float _pm3 = __shfl_up_sync(0xffffffffu, m13, 1);                         \
    int   _pE  = __shfl_up_sync(0xffffffffu, E1,  1);                         \
    if (lane == 0) _pE = EDEAD;                                               \
    float _om3 = m13; int _oE1 = E1;          /* old state 255 (lane 31) */   \
    float _pbe = pb##u + 1e-7f;                                               \
    QUPD(m10, m11, m12, m13, E1, m03, E0, k1b, k3b,                           \
         _pbe, la2##u + 1e-7f, la3##u + 1e-7f);                               \
    QUPD(m00, m01, m02, m03, E0, _pm3, _pE, k1a, k3a,                         \
         _pbe, la0##u + 1e-7f, la1##u + 1e-7f);                               \
    { /* state 256 (blank, no skip): alpha' = pb*(a256 + a255_old) */         \
        int   _em = max(e9, _oE1);                                            \
        float _s  = fmaf(m9, p2f(e9 - _em), _om3 * p2f(_oE1 - _em));          \
        float _v  = _pbe * _s;                                                \
        int _bits = __float_as_int(_v);                                       \
        int _ef9  = _bits >> 23;                                              \
        e9 = _em + _ef9 - 127;                                                \
        m9 = _v * __int_as_float((254 - _ef9) << 23);                         \
    }                                                                         \
    { /* refill bank u with frame tcur+4 */                                   \
        int _tf = (tcur) + 4; if (_tf > Tn - 1) _tf = Tn - 1;                 \
        const float* __restrict__ _rr = row + (size_t)_tf * Cn;               \
        pb##u  = __ldg(_rr + (Cn - 1));                                       \
        la0##u = __ldg(_rr + c0); la1##u = __ldg(_rr + c1);                   \
        la2##u = __ldg(_rr + c2); la3##u = __ldg(_rr + c3);                   \
    }                                                                         \
} while (0)

__global__ void __launch_bounds__(64)
ctc_quad_kernel(const int* __restrict__ labels,
                const float* __restrict__ ypred,
                float* __restrict__ out)
{
    const int lane = threadIdx.x & 31;
    const int warp = threadIdx.x >> 5;
    const int b    = blockIdx.x * 2 + warp;          // one batch element per warp
    const float* __restrict__ row = ypred + (size_t)b * (size_t)(Tn * Cn);

    // Lane l owns states 8l..8l+7 (two quads) -> labels 4l..4l+3; lane 31
    // additionally owns state 256 (final blank) as a scalar.
    const int* __restrict__ lab = labels + b * Ln;
    const int c0 = __ldg(lab + 4 * lane + 0);
    const int c1 = __ldg(lab + 4 * lane + 1);
    const int c2 = __ldg(lab + 4 * lane + 2);
    const int c3 = __ldg(lab + 4 * lane + 3);
    const int cm1 = __shfl_up_sync(0xffffffffu, c3, 1);  // label 4l-1

    // Skip-transition flags (odd states s>=3 with distinct labels)
    const float k1a = (lane > 0 && c0 != cm1) ? 1.0f : 0.0f;  // state 8l+1
    const float k3a = (c1 != c0) ? 1.0f : 0.0f;               // state 8l+3
    const float k1b = (c2 != c1) ? 1.0f : 0.0f;               // state 8l+5
    const float k3b = (c3 != c2) ? 1.0f : 0.0f;               // state 8l+7

    // State registers: quad0 = states 8l..8l+3, quad1 = 8l+4..8l+7
    float m00 = 0.0f, m01 = 0.0f, m02 = 0.0f, m03 = 0.0f;
    float m10 = 0.0f, m11 = 0.0f, m12 = 0.0f, m13 = 0.0f;
    int   E0 = EDEAD, E1 = EDEAD;
    float m9 = 0.0f;  int e9 = EDEAD;                // state 256

    // t = 0 init: states 0,1 live (lane 0, quad 0)
    if (lane == 0) {
        float v0 = __ldg(row + (Cn - 1)) + 1e-7f;
        float v1 = __ldg(row + c0) + 1e-7f;
        float mx = fmaxf(v0, v1);
        int ef = __float_as_int(mx) >> 23;
        float scr = __int_as_float((254 - ef) << 23);
        E0 = ef - 127;
        m00 = v0 * scr;
        m01 = v1 * scr;
    }

    // Probability banks for frames 1..4 (blank + 4 labels each)
    float pb0, la00, la10, la20, la30;
    float pb1, la01, la11, la21, la31;
    float pb2, la02, la12, la22, la32;
    float pb3, la03, la13, la23, la33;
    {
        const float* r1 = row + 1 * Cn;
        const float* r2 = row + 2 * Cn;
        const float* r3 = row + 3 * Cn;
        const float* r4 = row + 4 * Cn;
        pb0 = __ldg(r1 + (Cn-1)); la00 = __ldg(r1+c0); la10 = __ldg(r1+c1); la20 = __ldg(r1+c2); la30 = __ldg(r1+c3);
        pb1 = __ldg(r2 + (Cn-1)); la01 = __ldg(r2+c0); la11 = __ldg(r2+c1); la21 = __ldg(r2+c2); la31 = __ldg(r2+c3);
        pb2 = __ldg(r3 + (Cn-1)); la02 = __ldg(r3+c0); la12 = __ldg(r3+c1); la22 = __ldg(r3+c2); la32 = __ldg(r3+c3);
        pb3 = __ldg(r4 + (Cn-1)); la03 = __ldg(r4+c0); la13 = __ldg(r4+c1); la23 = __ldg(r4+c2); la33 = __ldg(r4+c3);
    }

    // Main loop: t = 1 .. 1020 (255 x 4 steps), then 3 tail steps
    int t = 1;
    #pragma unroll 1
    for (int it = 0; it < (Tn - 4) / 4; ++it) {
        STEP(0, t);
        STEP(1, t + 1);
        STEP(2, t + 2);
        STEP(3, t + 3);
        t += 4;
    }
    STEP(0, Tn - 3);   // t = 1021
    STEP(1, Tn - 2);   // t = 1022
    STEP(2, Tn - 1);   // t = 1023

    // loss = -log(alpha[255] + alpha[256]); state 255 = lane31 quad1 m13/E1
    if (lane == 31) {
        int em = max(E1, e9);
        float tot = fmaf(m13, p2f(E1 - em), m9 * p2f(e9 - em));
        out[b] = -(logf(tot) + (float)em * 0.69314718055994530942f);
    }
}

extern "C" void kernel_launch(void* const* d_in, const int* in_sizes, int n_in,
                              void* d_out, int out_size)
{
    const int*   labels;
    const float* ypred;
    if (in_sizes[0] == Bn * Ln) {
        labels = (const int*)d_in[0];
        ypred  = (const float*)d_in[1];
    } else {
        labels = (const int*)d_in[1];
        ypred  = (const float*)d_in[0];
    }
    ctc_quad_kernel<<<Bn / 2, 64>>>(labels, ypred, (float*)d_out);
}

// round 5
// speedup vs baseline: 4.2048x; 1.8444x over previous
#include <cuda_runtime.h>
#include <math.h>

// Problem constants (fixed by the benchmark shapes)
#define Bn 256
#define Tn 1024
#define Cn 256          // classes, blank = Cn-1
#define Ln 128
#define EDEAD (-(1 << 28))
#define NCH 4           // ring chunks per element
#define CF 8            // frames per chunk
#define RING_F (NCH * CF * Cn)   // floats per element ring = 8192

// exact 2^d for d in [-126, 0]; 0.0f below (relative flush)
__device__ __forceinline__ float p2f(int d) {
    return (d > -127) ? __int_as_float((127 + d) << 23) : 0.0f;
}
__device__ __forceinline__ void bar_arrive64(int id) {
    asm volatile("bar.arrive %0, 64;" :: "r"(id) : "memory");
}
__device__ __forceinline__ void bar_wait64(int id) {
    asm volatile("bar.sync %0, 64;" :: "r"(id) : "memory");
}

// One forward step. OFF = compile-time frame offset (floats) within chunk.
// Lane owns states 8l..8l+7 (mantissas m0..m7, shared exponent E); lane 31
// additionally owns state 256 as scalar (m9,e9) computed redundantly on all
// lanes. Probabilities read from smem ring via pointers ab (blank), a0..a3.
#define STEP(OFF) do {                                                        \
    float pb = ab[OFF]; float q0 = a0[OFF]; float q1 = a1[OFF];               \
    float q2 = a2[OFF]; float q3 = a3[OFF];                                   \
    float om7 = m7; int oE = E;                                               \
    float pm7 = __shfl_up_sync(0xffffffffu, m7, 1);                           \
    int   pE  = __shfl_up_sync(0xffffffffu, E,  1);                           \
    if (lane == 0) pE = EDEAD;                                                \
    int emax = max(E, pE);                                                    \
    int d    = emax - E;                                                      \
    float scq = p2f(-d);                                                      \
    float scp = p2f(pE - emax);                                               \
    float x0 = m0 * scq, x1 = m1 * scq, y7 = pm7 * scp;                       \
    float n0 = x0 + y7;                                                       \
    float n1 = fmaf(k1, y7, x0) + x1;                                         \
    float u2 = m2 + m1;                                                       \
    float u3 = fmaf(k3, m1, m2) + m3;                                         \
    float u4 = m4 + m3;                                                       \
    float u5 = fmaf(k5, m3, m4) + m5;                                         \
    float u6 = m6 + m5;                                                       \
    float u7 = fmaf(k7, m5, m6) + m7;                                         \
    float w0 = pb * n0, w1 = q0 * n1;                                         \
    float w2 = pb * u2, w3 = q1 * u3;                                         \
    float w4 = pb * u4, w5 = q2 * u5;                                         \
    float w6 = pb * u6, w7 = q3 * u7;                                         \
    float mA = fmaxf(fmaxf(fmaxf(w2, w3), fmaxf(w4, w5)), fmaxf(w6, w7));     \
    float mx = fmaxf(fmaxf(w0, w1), mA * scq);                                \
    int ef = __float_as_int(mx) >> 23;                                        \
    float sB = __int_as_float((254 - ef) << 23);                              \
    float sA = p2f(127 - ef - d);                                             \
    E = emax + ef - 127;                                                      \
    m0 = w0 * sB; m1 = w1 * sB;                                               \
    m2 = w2 * sA; m3 = w3 * sA; m4 = w4 * sA;                                 \
    m5 = w5 * sA; m6 = w6 * sA; m7 = w7 * sA;                                 \
    /* state 256 (final blank): alpha' = pb * (a256 + a255_old) */            \
    int em9 = max(e9, oE);                                                    \
    float s9 = fmaf(m9, p2f(e9 - em9), om7 * p2f(oE - em9));                  \
    float v9 = pb * s9;                                                       \
    int ef9 = __float_as_int(v9) >> 23;                                       \
    e9 = em9 + ef9 - 127;                                                     \
    m9 = v9 * __int_as_float((254 - ef9) << 23);                              \
} while (0)

__global__ void __launch_bounds__(128, 1)
ctc_ws_kernel(const int* __restrict__ labels,
              const float* __restrict__ ypred,
              float* __restrict__ out)
{
    extern __shared__ float ring[];                 // 2 * 8192 floats (64KB)
    const int lane = threadIdx.x & 31;
    const int warp = threadIdx.x >> 5;

    if (warp >= 2) {
        // ---------------- LOADER: stream frames into the smem ring ----------
        const int p = warp - 2;
        const int b = blockIdx.x * 2 + p;
        const float4* __restrict__ src =
            (const float4*)(ypred + (size_t)b * (size_t)(Tn * Cn));
        float* rp = ring + p * RING_F;
        // chunk = 512 float4; frame = 64 float4; lane covers idx lane, 32+lane
        float4 ca[CF], cb[CF];
        #pragma unroll
        for (int f = 0; f < CF; ++f) {
            ca[f] = __ldg(src + f * 64 + lane);
            cb[f] = __ldg(src + f * 64 + 32 + lane);
        }
        #pragma unroll 1
        for (int ck = 0; ck < Tn / CF; ++ck) {
            float4 na[CF], nb[CF];
            int nk = (ck + 1 < Tn / CF) ? ck + 1 : ck;   // clamp (last unused)
            #pragma unroll
            for (int f = 0; f < CF; ++f) {
                na[f] = __ldg(src + nk * 512 + f * 64 + lane);
                nb[f] = __ldg(src + nk * 512 + f * 64 + 32 + lane);
            }
            int slot = ck & (NCH - 1);
            if (ck >= NCH) bar_wait64(p * 8 + 4 + slot);  // slot freed?
            float4* dst = (float4*)(rp + slot * (CF * Cn));
            #pragma unroll
            for (int f = 0; f < CF; ++f) {
                float4 a = ca[f], bb = cb[f];
                a.x += 1e-7f; a.y += 1e-7f; a.z += 1e-7f; a.w += 1e-7f;
                bb.x += 1e-7f; bb.y += 1e-7f; bb.z += 1e-7f; bb.w += 1e-7f;
                dst[f * 64 + lane] = a;
                dst[f * 64 + 32 + lane] = bb;
            }
            bar_arrive64(p * 8 + slot);                   // slot filled
            #pragma unroll
            for (int f = 0; f < CF; ++f) { ca[f] = na[f]; cb[f] = nb[f]; }
        }
        return;
    }

    // ---------------- COMPUTE: one warp per batch element --------------------
    const int p = warp;
    const int b = blockIdx.x * 2 + p;
    const float* __restrict__ row = ypred + (size_t)b * (size_t)(Tn * Cn);
    const int* __restrict__ lab = labels + b * Ln;
    const float* rp = ring + p * RING_F;

    const int c0 = __ldg(lab + 4 * lane + 0);
    const int c1 = __ldg(lab + 4 * lane + 1);
    const int c2 = __ldg(lab + 4 * lane + 2);
    const int c3 = __ldg(lab + 4 * lane + 3);
    const int cm1 = __shfl_up_sync(0xffffffffu, c3, 1);
    const float k1 = (lane > 0 && c0 != cm1) ? 1.0f : 0.0f;
    const float k3 = (c1 != c0) ? 1.0f : 0.0f;
    const float k5 = (c2 != c1) ? 1.0f : 0.0f;
    const float k7 = (c3 != c2) ? 1.0f : 0.0f;

    float m0 = 0.f, m1 = 0.f, m2 = 0.f, m3 = 0.f;
    float m4 = 0.f, m5 = 0.f, m6 = 0.f, m7 = 0.f;
    int E = EDEAD;
    float m9 = 0.f; int e9 = EDEAD;

    // t = 0 init: states 0 (blank) and 1 (label 0) live, lane 0 only
    {
        float v0 = __ldg(row + (Cn - 1)) + 1e-7f;
        float v1 = __ldg(row + c0) + 1e-7f;
        float mx = fmaxf(v0, v1);
        int ef = __float_as_int(mx) >> 23;
        float scr = __int_as_float((254 - ef) << 23);
        if (lane == 0) { E = ef - 127; m0 = v0 * scr; m1 = v1 * scr; }
    }

    // Chunk 0: frames 1..7
    {
        bar_wait64(p * 8 + 0);
        const float* base = rp;                       // slot 0
        const float* ab = base + (Cn - 1);
        const float* a0 = base + c0; const float* a1 = base + c1;
        const float* a2 = base + c2; const float* a3 = base + c3;
        STEP(1 * Cn); STEP(2 * Cn); STEP(3 * Cn); STEP(4 * Cn);
        STEP(5 * Cn); STEP(6 * Cn); STEP(7 * Cn);
        bar_arrive64(p * 8 + 4 + 0);
    }
    // Chunks 1..127: 8 frames each
    #pragma unroll 1
    for (int ck = 1; ck < Tn / CF; ++ck) {
        int slot = ck & (NCH - 1);
        bar_wait64(p * 8 + slot);
        const float* base = rp + slot * (CF * Cn);
        const float* ab = base + (Cn - 1);
        const float* a0 = base + c0; const float* a1 = base + c1;
        const float* a2 = base + c2; const float* a3 = base + c3;
        STEP(0 * Cn); STEP(1 * Cn); STEP(2 * Cn); STEP(3 * Cn);
        STEP(4 * Cn); STEP(5 * Cn); STEP(6 * Cn); STEP(7 * Cn);
        bar_arrive64(p * 8 + 4 + slot);
    }

    // loss = -log(alpha[255] + alpha[256]); both live on lane 31
    if (lane == 31) {
        int em = max(E, e9);
        float tot = fmaf(m7, p2f(E - em), m9 * p2f(e9 - em));
        out[b] = -(logf(tot) + (float)em * 0.69314718055994530942f);
    }
}

extern "C" void kernel_launch(void* const* d_in, const int* in_sizes, int n_in,
                              void* d_out, int out_size)
{
    const int*   labels;
    const float* ypred;
    if (in_sizes[0] == Bn * Ln) {
        labels = (const int*)d_in[0];
        ypred  = (const float*)d_in[1];
    } else {
        labels = (const int*)d_in[1];
        ypred  = (const float*)d_in[0];
    }
    const int smem = 2 * RING_F * (int)sizeof(float);   // 64 KB
    cudaFuncSetAttribute(ctc_ws_kernel,
                         cudaFuncAttributeMaxDynamicSharedMemorySize, smem);
    ctc_ws_kernel<<<Bn / 2, 128, smem>>>(labels, ypred, (float*)d_out);
}